// round 2
// baseline (speedup 1.0000x reference)
#include <cuda_runtime.h>
#include <cuda_bf16.h>
#include <math.h>

#define Bb 32
#define Cc 512
#define Ll 1024
#define CL (Cc*Ll)

// Scratch (device globals: allocation-free per harness rules)
__device__ float g_conv[Bb*Cc*Ll];          // conv output [B,C,L], 64MB
__device__ float g_mean[Cc];
__device__ float g_rstd[Cc];
__device__ int   g_qact[Bb*Ll*(Cc/4)];      // packed int8 activations [B,L,C/4]
__device__ float g_ascale[Bb*Ll];           // per-token dequant scale = clip(amax)/127
__device__ int   g_qw[Cc*(Cc/4)];           // packed ternary weights [O,C/4]
__device__ double g_wpart[64];
__device__ float g_wmean;                   // clip(mean|w|, 1e-5)

__device__ __forceinline__ unsigned long long pk2(float a, float b){
    unsigned long long r;
    asm("mov.b64 %0, {%1,%2};" : "=l"(r) : "f"(a), "f"(b));
    return r;
}
__device__ __forceinline__ void upk2(unsigned long long v, float &a, float &b){
    asm("mov.b64 {%0,%1}, %2;" : "=f"(a), "=f"(b) : "l"(v));
}
// Packed fp32x2 FMA (sm_100+/sm_103a; FFMA2 in SASS — 2x fp32 throughput)
__device__ __forceinline__ unsigned long long ffma2(unsigned long long a,
                                                    unsigned long long b,
                                                    unsigned long long c){
    unsigned long long d;
    asm("fma.rn.f32x2 %0, %1, %2, %3;" : "=l"(d) : "l"(a), "l"(b), "l"(c));
    return d;
}
__device__ __forceinline__ float gelu_exact(float x){
    return 0.5f * x * (1.0f + erff(x * 0.70710678118654752f));
}

// ---------------------------------------------------------------------------
// Conv1d k=3 pad=1 + bias -> g_conv.  Tile: 128 Cout x 64 L per block (128 thr),
// thread: 8c (4 packed pairs) x 8l, K-chunks of 16 input channels.
// ---------------------------------------------------------------------------
__global__ __launch_bounds__(128) void conv_kernel(const float* __restrict__ x,
                                                   const float* __restrict__ w,
                                                   const float* __restrict__ bias)
{
    __shared__ __align__(16) unsigned long long xs[16][8][10]; // x dup-packed, per l-group
    __shared__ __align__(16) float wsf[16][3][128];            // w[ci][k][cout]

    const int b  = blockIdx.z;
    const int c0 = blockIdx.y * 128;
    const int l0 = blockIdx.x * 64;
    const int tid = threadIdx.x;
    const int tx = tid & 7;    // l-group
    const int ty = tid >> 3;   // c-group (0..15)

    unsigned long long acc[4][8];
    #pragma unroll
    for (int i = 0; i < 4; i++)
        #pragma unroll
        for (int j = 0; j < 8; j++) acc[i][j] = 0ull;

    const float* xb = x + b * CL;
    const unsigned long long* wsu = reinterpret_cast<const unsigned long long*>(&wsf[0][0][0]);

    for (int ci0 = 0; ci0 < Cc; ci0 += 16) {
        // --- load x tile (with halo, duplicated into both f32x2 lanes) ---
        for (int idx = tid; idx < 1280; idx += 128) {
            int ci = idx / 80;
            int r  = idx - ci * 80;
            int t  = r / 10;
            int j  = r - t * 10;
            int gl = l0 + t * 8 + j - 1;
            float v = (gl >= 0 && gl < Ll) ? xb[(ci0 + ci) * Ll + gl] : 0.0f;
            xs[ci][t][j] = pk2(v, v);
        }
        // --- load w tile: contiguous float4 per cout row, scatter to [ci][k][c] ---
        for (int idx = tid; idx < 1536; idx += 128) {
            int c = idx / 12;
            int q = idx - c * 12;
            const float4 v = *reinterpret_cast<const float4*>(
                w + (c0 + c) * (Cc * 3) + ci0 * 3 + q * 4);
            float vv[4] = {v.x, v.y, v.z, v.w};
            #pragma unroll
            for (int s = 0; s < 4; s++) {
                int ee = q * 4 + s;
                int ci = ee / 3, k = ee - ci * 3;
                wsf[ci][k][c] = vv[s];
            }
        }
        __syncthreads();

        #pragma unroll 2
        for (int kk = 0; kk < 16; kk++) {
            unsigned long long xp[10];
            #pragma unroll
            for (int j = 0; j < 10; j++) xp[j] = xs[kk][tx][j];
            #pragma unroll
            for (int i = 0; i < 4; i++) {
                const int base = kk * 192 + ty + 16 * i; // ull index: pair (2ty+32i, +1)
                unsigned long long w0 = wsu[base];
                unsigned long long w1 = wsu[base + 64];
                unsigned long long w2 = wsu[base + 128];
                #pragma unroll
                for (int j = 0; j < 8; j++) {
                    acc[i][j] = ffma2(w0, xp[j],     acc[i][j]);
                    acc[i][j] = ffma2(w1, xp[j + 1], acc[i][j]);
                    acc[i][j] = ffma2(w2, xp[j + 2], acc[i][j]);
                }
            }
        }
        __syncthreads();
    }

    // epilogue: unpack pairs, add bias, coalesced float4 stores
    float* ob = g_conv + b * CL;
    #pragma unroll
    for (int i = 0; i < 4; i++) {
        int cE = c0 + ty * 2 + 32 * i;
        float r0[8], r1[8];
        #pragma unroll
        for (int j = 0; j < 8; j++) upk2(acc[i][j], r0[j], r1[j]);
        float b0 = bias[cE], b1 = bias[cE + 1];
        float4 v;
        v = make_float4(r0[0]+b0, r0[1]+b0, r0[2]+b0, r0[3]+b0);
        *reinterpret_cast<float4*>(ob + cE * Ll + l0 + tx * 8) = v;
        v = make_float4(r0[4]+b0, r0[5]+b0, r0[6]+b0, r0[7]+b0);
        *reinterpret_cast<float4*>(ob + cE * Ll + l0 + tx * 8 + 4) = v;
        v = make_float4(r1[0]+b1, r1[1]+b1, r1[2]+b1, r1[3]+b1);
        *reinterpret_cast<float4*>(ob + (cE + 1) * Ll + l0 + tx * 8) = v;
        v = make_float4(r1[4]+b1, r1[5]+b1, r1[6]+b1, r1[7]+b1);
        *reinterpret_cast<float4*>(ob + (cE + 1) * Ll + l0 + tx * 8 + 4) = v;
    }
}

// ---------------------------------------------------------------------------
// Per-channel batch stats (mean, rstd) over B*L = 32768 samples. 1 block/channel.
// ---------------------------------------------------------------------------
__global__ __launch_bounds__(256) void stats_kernel()
{
    const int c = blockIdx.x;
    const int tid = threadIdx.x;
    double s = 0.0, s2 = 0.0;
    for (int b = 0; b < Bb; b++) {
        const float4 v = reinterpret_cast<const float4*>(g_conv + b * CL + c * Ll)[tid];
        s  += (double)v.x + (double)v.y + (double)v.z + (double)v.w;
        s2 += (double)v.x * v.x + (double)v.y * v.y + (double)v.z * v.z + (double)v.w * v.w;
    }
    #pragma unroll
    for (int o = 16; o; o >>= 1) {
        s  += __shfl_down_sync(0xffffffffu, s, o);
        s2 += __shfl_down_sync(0xffffffffu, s2, o);
    }
    __shared__ double sh[16];
    if ((tid & 31) == 0) { sh[tid >> 5] = s; sh[8 + (tid >> 5)] = s2; }
    __syncthreads();
    if (tid == 0) {
        double ts = 0, ts2 = 0;
        for (int i = 0; i < 8; i++) { ts += sh[i]; ts2 += sh[8 + i]; }
        double mean = ts / 32768.0;
        double var  = ts2 / 32768.0 - mean * mean;
        g_mean[c] = (float)mean;
        g_rstd[c] = rsqrtf((float)var + 1e-5f);
    }
}

// ---------------------------------------------------------------------------
// Weight absmean (2-stage) + ternary quant/pack
// ---------------------------------------------------------------------------
__global__ __launch_bounds__(256) void wred1_kernel(const float* __restrict__ w)
{
    const int tid = threadIdx.x;
    const int base = blockIdx.x * 4096;
    double s = 0.0;
    for (int i = tid; i < 4096; i += 256) s += (double)fabsf(w[base + i]);
    #pragma unroll
    for (int o = 16; o; o >>= 1) s += __shfl_down_sync(0xffffffffu, s, o);
    __shared__ double sh[8];
    if ((tid & 31) == 0) sh[tid >> 5] = s;
    __syncthreads();
    if (tid == 0) {
        double t = 0; for (int i = 0; i < 8; i++) t += sh[i];
        g_wpart[blockIdx.x] = t;
    }
}
__global__ void wred2_kernel()
{
    const int tid = threadIdx.x; // 64
    double s = g_wpart[tid];
    #pragma unroll
    for (int o = 16; o; o >>= 1) s += __shfl_down_sync(0xffffffffu, s, o);
    __shared__ double sh[2];
    if ((tid & 31) == 0) sh[tid >> 5] = s;
    __syncthreads();
    if (tid == 0) {
        float mean = (float)((sh[0] + sh[1]) / 262144.0);
        g_wmean = fmaxf(mean, 1e-5f);
    }
}
__global__ __launch_bounds__(256) void wquant_kernel(const float* __restrict__ w)
{
    const int g = blockIdx.x * 256 + threadIdx.x; // 65536 groups of 4
    const float inv = 1.0f / g_wmean;
    const float4 v = reinterpret_cast<const float4*>(w)[g];
    int a = max(-1, min(1, (int)rintf(v.x * inv)));
    int b = max(-1, min(1, (int)rintf(v.y * inv)));
    int c = max(-1, min(1, (int)rintf(v.z * inv)));
    int d = max(-1, min(1, (int)rintf(v.w * inv)));
    g_qw[g] = (a & 0xff) | ((b & 0xff) << 8) | ((c & 0xff) << 16) | ((d & 0xff) << 24);
}

// ---------------------------------------------------------------------------
// BN + GELU + per-token absmax int8 quant. Block: (b, 8 tokens). Warp per token.
// ---------------------------------------------------------------------------
__global__ __launch_bounds__(256) void bnq_kernel(const float* __restrict__ gamma,
                                                  const float* __restrict__ beta)
{
    const int b  = blockIdx.y;
    const int l0 = blockIdx.x * 8;
    const int tid = threadIdx.x;
    __shared__ float sv[512][9];
    __shared__ unsigned char qs[8][512];

    {
        const int c = tid >> 1;
        const int half = tid & 1;
        #pragma unroll
        for (int it = 0; it < 4; it++) {
            int cc = c + it * 128;
            float4 v = *reinterpret_cast<const float4*>(
                g_conv + b * CL + cc * Ll + l0 + half * 4);
            sv[cc][half*4+0] = v.x; sv[cc][half*4+1] = v.y;
            sv[cc][half*4+2] = v.z; sv[cc][half*4+3] = v.w;
        }
    }
    __syncthreads();

    const int wrp  = tid >> 5;  // token 0..7
    const int lane = tid & 31;
    float mx = 0.0f;
    #pragma unroll
    for (int i = 0; i < 16; i++) {
        int c = lane + 32 * i;
        float v = sv[c][wrp];
        v = (v - g_mean[c]) * g_rstd[c];
        v = v * gamma[c] + beta[c];
        v = gelu_exact(v);
        sv[c][wrp] = v;
        mx = fmaxf(mx, fabsf(v));
    }
    #pragma unroll
    for (int o = 16; o; o >>= 1) mx = fmaxf(mx, __shfl_xor_sync(0xffffffffu, mx, o));
    float amax = fmaxf(mx, 1e-5f);
    float qscale = 127.0f / amax;
    if (lane == 0) g_ascale[b * Ll + l0 + wrp] = amax * (1.0f / 127.0f);
    #pragma unroll
    for (int i = 0; i < 16; i++) {
        int c = lane + 32 * i;
        float q = rintf(sv[c][wrp] * qscale);
        q = fminf(fmaxf(q, -128.0f), 127.0f);
        qs[wrp][c] = (unsigned char)(signed char)(int)q;
    }
    __syncthreads();

    for (int idx = tid; idx < 1024; idx += 256) {
        int t = idx >> 7;
        int g = idx & 127;
        uchar4 u = *reinterpret_cast<const uchar4*>(&qs[t][g * 4]);
        int packed = (int)u.x | ((int)u.y << 8) | ((int)u.z << 16) | ((int)u.w << 24);
        g_qact[(b * Ll + l0 + t) * 128 + g] = packed;
    }
}

// ---------------------------------------------------------------------------
// BitLinear int8 GEMM (dp4a, exact) + gelu + residual. Tile 64o x 64l, thr 4x4.
// ---------------------------------------------------------------------------
__global__ __launch_bounds__(256) void gemm_kernel(const float* __restrict__ x,
                                                   float* __restrict__ out)
{
    const int b  = blockIdx.z;
    const int o0 = blockIdx.y * 64;
    const int l0 = blockIdx.x * 64;
    const int tid = threadIdx.x;
    const int tx = tid & 15;   // l
    const int ty = tid >> 4;   // o
    __shared__ int qsm[64][17];
    __shared__ int tsm[64][17];
    int acc[4][4] = {};

    for (int kc = 0; kc < 128; kc += 16) {
        for (int idx = tid; idx < 1024; idx += 256) {
            int r = idx >> 4, k = idx & 15;
            qsm[r][k] = g_qact[(b * Ll + l0 + r) * 128 + kc + k];
            tsm[r][k] = g_qw[(o0 + r) * 128 + kc + k];
        }
        __syncthreads();
        #pragma unroll
        for (int k = 0; k < 16; k++) {
            int qv[4], tv[4];
            #pragma unroll
            for (int j = 0; j < 4; j++) qv[j] = qsm[tx * 4 + j][k];
            #pragma unroll
            for (int i = 0; i < 4; i++) tv[i] = tsm[ty * 4 + i][k];
            #pragma unroll
            for (int i = 0; i < 4; i++)
                #pragma unroll
                for (int j = 0; j < 4; j++)
                    acc[i][j] = __dp4a(qv[j], tv[i], acc[i][j]);
        }
        __syncthreads();
    }

    const float wm = g_wmean;
    float as[4];
    #pragma unroll
    for (int j = 0; j < 4; j++) as[j] = g_ascale[b * Ll + l0 + tx * 4 + j] * wm;
    #pragma unroll
    for (int i = 0; i < 4; i++) {
        int o = o0 + ty * 4 + i;
        const float4 xr = *reinterpret_cast<const float4*>(
            x + b * CL + o * Ll + l0 + tx * 4);
        float4 r;
        r.x = gelu_exact((float)acc[i][0] * as[0]) + xr.x;
        r.y = gelu_exact((float)acc[i][1] * as[1]) + xr.y;
        r.z = gelu_exact((float)acc[i][2] * as[2]) + xr.z;
        r.w = gelu_exact((float)acc[i][3] * as[3]) + xr.w;
        *reinterpret_cast<float4*>(out + b * CL + o * Ll + l0 + tx * 4) = r;
    }
}

// ---------------------------------------------------------------------------
extern "C" void kernel_launch(void* const* d_in, const int* in_sizes, int n_in,
                              void* d_out, int out_size)
{
    const float* x      = (const float*)d_in[0];
    const float* conv_w = (const float*)d_in[1];
    const float* conv_b = (const float*)d_in[2];
    const float* gamma  = (const float*)d_in[3];
    const float* beta   = (const float*)d_in[4];
    const float* proj_w = (const float*)d_in[5];
    float* out = (float*)d_out;

    conv_kernel<<<dim3(16, 4, 32), 128>>>(x, conv_w, conv_b);
    stats_kernel<<<512, 256>>>();
    wred1_kernel<<<64, 256>>>(proj_w);
    wred2_kernel<<<1, 64>>>();
    wquant_kernel<<<256, 256>>>(proj_w);
    bnq_kernel<<<dim3(128, 32), 256>>>(gamma, beta);
    gemm_kernel<<<dim3(16, 8, 32), 256>>>(x, out);
}

// round 7
// speedup vs baseline: 2.0162x; 2.0162x over previous
#include <cuda_runtime.h>
#include <cuda_bf16.h>
#include <math.h>
#include <stdint.h>

#define Bb 32
#define Cc 512
#define Ll 1024
#define CL (Cc*Ll)

// ---------------- device globals (allocation-free scratch) ----------------
__device__ uint4 g_xs4[(Bb*Ll*1024*2)/16];   // bf16 [b][l][kk], kk<512: xhi[ci], kk>=512: xlo[ci]
__device__ uint4 g_wa4[(3*Cc*1024*2)/16];    // bf16 [k][co][kk], kk<512: whi[ci], kk>=512: wlo[ci]
__device__ float g_conv[Bb*Cc*Ll];           // conv output [B,C,L]
__device__ float g_mean[Cc];
__device__ float g_rstd[Cc];
__device__ int   g_qact[Bb*Ll*(Cc/4)];       // packed int8 activations [B,L,C/4]
__device__ float g_ascale[Bb*Ll];            // per-token dequant scale
__device__ int   g_qw[Cc*(Cc/4)];            // packed ternary weights [O,C/4]
__device__ double g_wpart[64];
__device__ float g_wmean;

__device__ __forceinline__ float gelu_exact(float x){
    return 0.5f * x * (1.0f + erff(x * 0.70710678118654752f));
}

// mma.sync m16n8k16 bf16 (PTX generic sm_80+, compiles for compute_103)
__device__ __forceinline__ void mma16816(float* c, const uint32_t* a, const uint32_t* b){
    asm("mma.sync.aligned.m16n8k16.row.col.f32.bf16.bf16.f32 "
        "{%0,%1,%2,%3}, {%4,%5,%6,%7}, {%8,%9}, {%0,%1,%2,%3};"
        : "+f"(c[0]), "+f"(c[1]), "+f"(c[2]), "+f"(c[3])
        : "r"(a[0]), "r"(a[1]), "r"(a[2]), "r"(a[3]), "r"(b[0]), "r"(b[1]));
}

// ---------------------------------------------------------------------------
// x split+transpose: [B,C,L] fp32 -> bf16 hi/lo at [b][l][kk]
// ---------------------------------------------------------------------------
__global__ __launch_bounds__(256) void xsplit_kernel(const float* __restrict__ x)
{
    __shared__ float t[64][65];
    const int b = blockIdx.z, c0 = blockIdx.y * 64, l0 = blockIdx.x * 64;
    const int tid = threadIdx.x;
    const float* xb = x + (size_t)b * CL;
    #pragma unroll
    for (int i = 0; i < 16; i++){
        int idx = tid + i * 256;
        int c = idx >> 6, l = idx & 63;
        t[c][l] = xb[(size_t)(c0 + c) * Ll + l0 + l];
    }
    __syncthreads();
    __nv_bfloat16* xs = (__nv_bfloat16*)g_xs4;
    #pragma unroll
    for (int i = 0; i < 8; i++){
        int idx = tid + i * 256;
        int l = idx >> 5, c = (idx & 31) * 2;
        float v0 = t[c][l], v1 = t[c + 1][l];
        __nv_bfloat16 h0 = __float2bfloat16_rn(v0);
        __nv_bfloat16 h1 = __float2bfloat16_rn(v1);
        __nv_bfloat16 q0 = __float2bfloat16_rn(v0 - __bfloat162float(h0));
        __nv_bfloat16 q1 = __float2bfloat16_rn(v1 - __bfloat162float(h1));
        size_t base = ((size_t)b * Ll + l0 + l) * 1024;
        __nv_bfloat162 ph; ph.x = h0; ph.y = h1;
        __nv_bfloat162 pl; pl.x = q0; pl.y = q1;
        *(__nv_bfloat162*)(xs + base + c0 + c) = ph;
        *(__nv_bfloat162*)(xs + base + 512 + c0 + c) = pl;
    }
}

// ---------------------------------------------------------------------------
// w split: [co][ci][k] fp32 -> bf16 hi/lo at [k][co][kk]
// ---------------------------------------------------------------------------
__global__ __launch_bounds__(256) void wsplit_kernel(const float* __restrict__ w)
{
    const int co = blockIdx.x;
    const int ci = threadIdx.x * 2;
    __nv_bfloat16* wa = (__nv_bfloat16*)g_wa4;
    #pragma unroll
    for (int k = 0; k < 3; k++){
        float v0 = w[((size_t)co * Cc + ci) * 3 + k];
        float v1 = w[((size_t)co * Cc + ci + 1) * 3 + k];
        __nv_bfloat16 h0 = __float2bfloat16_rn(v0);
        __nv_bfloat16 h1 = __float2bfloat16_rn(v1);
        __nv_bfloat16 q0 = __float2bfloat16_rn(v0 - __bfloat162float(h0));
        __nv_bfloat16 q1 = __float2bfloat16_rn(v1 - __bfloat162float(h1));
        size_t base = ((size_t)k * Cc + co) * 1024;
        __nv_bfloat162 ph; ph.x = h0; ph.y = h1;
        __nv_bfloat162 pl; pl.x = q0; pl.y = q1;
        *(__nv_bfloat162*)(wa + base + ci) = ph;
        *(__nv_bfloat162*)(wa + base + 512 + ci) = pl;
    }
}

// ---------------------------------------------------------------------------
// Conv via mma.sync bf16 (hi/lo split, 3 product planes).
// Block tile: 128 co x 256 l. 8 warps, warp tile 64x64.
// K: 3 shifts x 512 ci, smem-chunked 64 ci. B smem = [l+halo][ci] so the
// shift is a pure row offset (one B load serves all 3 shifts).
// ---------------------------------------------------------------------------
#define SM_B_HI 0
#define SM_B_LO 18576              // 258*72
#define SM_A_HI 37152
#define SM_A_LO 64800              // + 3*128*72
#define CONV_SMEM (92448*2)        // 184,896 bytes

__global__ __launch_bounds__(256) void conv_mma_kernel(const float* __restrict__ bias)
{
    extern __shared__ __align__(16) __nv_bfloat16 sm[];
    __nv_bfloat16* Bh = sm + SM_B_HI;
    __nv_bfloat16* Bl = sm + SM_B_LO;
    __nv_bfloat16* Ah = sm + SM_A_HI;
    __nv_bfloat16* Al = sm + SM_A_LO;

    const int tid = threadIdx.x;
    const int wid = tid >> 5;
    const int lane = tid & 31;
    const int tq = lane >> 2;    // t/4
    const int tr = lane & 3;     // t%4
    const int wc = (wid >> 2) * 64;   // warp co offset
    const int wl = (wid & 3) * 64;    // warp l offset
    const int b   = blockIdx.z;
    const int co0 = blockIdx.y * 128;
    const int l0  = blockIdx.x * 256;

    float acc[4][8][4];
    #pragma unroll
    for (int i = 0; i < 4; i++)
        #pragma unroll
        for (int j = 0; j < 8; j++)
            #pragma unroll
            for (int q = 0; q < 4; q++) acc[i][j][q] = 0.0f;

    for (int c0 = 0; c0 < 512; c0 += 64){
        // ---- B tile: 258 rows (l0-1 .. l0+256) x 64 ci, hi+lo ----
        for (int idx = tid; idx < 4128; idx += 256){
            int row = idx >> 4, part = idx & 15;
            int lrow = l0 - 1 + row;
            int kk = (part & 7) * 8 + c0 + ((part & 8) ? 512 : 0);
            uint4 v = make_uint4(0u, 0u, 0u, 0u);
            if (lrow >= 0 && lrow < Ll)
                v = g_xs4[(((size_t)b * Ll + lrow) * 1024 + kk) >> 3];
            __nv_bfloat16* dst = (part & 8) ? Bl : Bh;
            *(uint4*)(dst + row * 72 + (part & 7) * 8) = v;
        }
        // ---- A tile: 3 shifts x 128 co x 64 ci, hi+lo ----
        for (int idx = tid; idx < 6144; idx += 256){
            int row = idx >> 4, part = idx & 15;   // row = k*128 + r
            int k = row >> 7, r = row & 127;
            int kk = (part & 7) * 8 + c0 + ((part & 8) ? 512 : 0);
            uint4 v = g_wa4[(((size_t)(k * 512 + co0 + r)) * 1024 + kk) >> 3];
            __nv_bfloat16* dst = (part & 8) ? Al : Ah;
            *(uint4*)(dst + row * 72 + (part & 7) * 8) = v;
        }
        __syncthreads();

        for (int s = 0; s < 3; s++){
            #pragma unroll
            for (int ks = 0; ks < 4; ks++){
                const int kb = ks * 16 + tr * 2;
                uint32_t bhv[8][2], blv[8][2];
                #pragma unroll
                for (int j = 0; j < 8; j++){
                    int row = wl + j * 8 + tq + s;
                    const __nv_bfloat16* ph = Bh + row * 72 + kb;
                    const __nv_bfloat16* pl = Bl + row * 72 + kb;
                    bhv[j][0] = *(const uint32_t*)ph;
                    bhv[j][1] = *(const uint32_t*)(ph + 8);
                    blv[j][0] = *(const uint32_t*)pl;
                    blv[j][1] = *(const uint32_t*)(pl + 8);
                }
                #pragma unroll
                for (int i = 0; i < 4; i++){
                    const int m = s * 128 + wc + i * 16 + tq;
                    const __nv_bfloat16* pa = Ah + m * 72 + kb;
                    const __nv_bfloat16* pb = Al + m * 72 + kb;
                    uint32_t ah[4], al[4];
                    ah[0] = *(const uint32_t*)pa;
                    ah[1] = *(const uint32_t*)(pa + 8 * 72);
                    ah[2] = *(const uint32_t*)(pa + 8);
                    ah[3] = *(const uint32_t*)(pa + 8 * 72 + 8);
                    al[0] = *(const uint32_t*)pb;
                    al[1] = *(const uint32_t*)(pb + 8 * 72);
                    al[2] = *(const uint32_t*)(pb + 8);
                    al[3] = *(const uint32_t*)(pb + 8 * 72 + 8);
                    #pragma unroll
                    for (int j = 0; j < 8; j++){
                        mma16816(acc[i][j], ah, bhv[j]);   // hi*hi
                        mma16816(acc[i][j], ah, blv[j]);   // hi*lo
                        mma16816(acc[i][j], al, bhv[j]);   // lo*hi
                    }
                }
            }
        }
        __syncthreads();
    }

    // ---- epilogue: + bias -> g_conv ----
    #pragma unroll
    for (int i = 0; i < 4; i++){
        int r0 = co0 + wc + i * 16 + tq;
        float b0 = bias[r0], b1 = bias[r0 + 8];
        float* base0 = g_conv + ((size_t)b * Cc + r0) * Ll + l0 + wl;
        float* base1 = base0 + (size_t)8 * Ll;
        #pragma unroll
        for (int j = 0; j < 8; j++){
            int cc = j * 8 + tr * 2;
            float2 v0; v0.x = acc[i][j][0] + b0; v0.y = acc[i][j][1] + b0;
            *(float2*)(base0 + cc) = v0;
            float2 v1; v1.x = acc[i][j][2] + b1; v1.y = acc[i][j][3] + b1;
            *(float2*)(base1 + cc) = v1;
        }
    }
}

// ---------------------------------------------------------------------------
// Per-channel batch stats (mean, rstd) over B*L = 32768 samples.
// ---------------------------------------------------------------------------
__global__ __launch_bounds__(256) void stats_kernel()
{
    const int c = blockIdx.x;
    const int tid = threadIdx.x;
    double s = 0.0, s2 = 0.0;
    for (int b = 0; b < Bb; b++) {
        const float4 v = reinterpret_cast<const float4*>(g_conv + (size_t)b * CL + (size_t)c * Ll)[tid];
        s  += (double)v.x + (double)v.y + (double)v.z + (double)v.w;
        s2 += (double)v.x * v.x + (double)v.y * v.y + (double)v.z * v.z + (double)v.w * v.w;
    }
    #pragma unroll
    for (int o = 16; o; o >>= 1) {
        s  += __shfl_down_sync(0xffffffffu, s, o);
        s2 += __shfl_down_sync(0xffffffffu, s2, o);
    }
    __shared__ double sh[16];
    if ((tid & 31) == 0) { sh[tid >> 5] = s; sh[8 + (tid >> 5)] = s2; }
    __syncthreads();
    if (tid == 0) {
        double ts = 0, ts2 = 0;
        for (int i = 0; i < 8; i++) { ts += sh[i]; ts2 += sh[8 + i]; }
        double mean = ts / 32768.0;
        double var  = ts2 / 32768.0 - mean * mean;
        g_mean[c] = (float)mean;
        g_rstd[c] = rsqrtf((float)var + 1e-5f);
    }
}

// ---------------------------------------------------------------------------
// Weight absmean (2-stage) + ternary quant/pack
// ---------------------------------------------------------------------------
__global__ __launch_bounds__(256) void wred1_kernel(const float* __restrict__ w)
{
    const int tid = threadIdx.x;
    const int base = blockIdx.x * 4096;
    double s = 0.0;
    for (int i = tid; i < 4096; i += 256) s += (double)fabsf(w[base + i]);
    #pragma unroll
    for (int o = 16; o; o >>= 1) s += __shfl_down_sync(0xffffffffu, s, o);
    __shared__ double sh[8];
    if ((tid & 31) == 0) sh[tid >> 5] = s;
    __syncthreads();
    if (tid == 0) {
        double t = 0; for (int i = 0; i < 8; i++) t += sh[i];
        g_wpart[blockIdx.x] = t;
    }
}
__global__ void wred2_kernel()
{
    const int tid = threadIdx.x; // 64
    double s = g_wpart[tid];
    #pragma unroll
    for (int o = 16; o; o >>= 1) s += __shfl_down_sync(0xffffffffu, s, o);
    __shared__ double sh[2];
    if ((tid & 31) == 0) sh[tid >> 5] = s;
    __syncthreads();
    if (tid == 0) {
        float mean = (float)((sh[0] + sh[1]) / 262144.0);
        g_wmean = fmaxf(mean, 1e-5f);
    }
}
__global__ __launch_bounds__(256) void wquant_kernel(const float* __restrict__ w)
{
    const int g = blockIdx.x * 256 + threadIdx.x;
    const float inv = 1.0f / g_wmean;
    const float4 v = reinterpret_cast<const float4*>(w)[g];
    int a = max(-1, min(1, (int)rintf(v.x * inv)));
    int b = max(-1, min(1, (int)rintf(v.y * inv)));
    int c = max(-1, min(1, (int)rintf(v.z * inv)));
    int d = max(-1, min(1, (int)rintf(v.w * inv)));
    g_qw[g] = (a & 0xff) | ((b & 0xff) << 8) | ((c & 0xff) << 16) | ((d & 0xff) << 24);
}

// ---------------------------------------------------------------------------
// BN + GELU + per-token absmax int8 quant. Block: (b, 8 tokens). Warp per token.
// ---------------------------------------------------------------------------
__global__ __launch_bounds__(256) void bnq_kernel(const float* __restrict__ gamma,
                                                  const float* __restrict__ beta)
{
    const int b  = blockIdx.y;
    const int l0 = blockIdx.x * 8;
    const int tid = threadIdx.x;
    __shared__ float sv[512][9];
    __shared__ unsigned char qs[8][512];

    {
        const int c = tid >> 1;
        const int half = tid & 1;
        #pragma unroll
        for (int it = 0; it < 4; it++) {
            int cc = c + it * 128;
            float4 v = *reinterpret_cast<const float4*>(
                g_conv + (size_t)b * CL + (size_t)cc * Ll + l0 + half * 4);
            sv[cc][half*4+0] = v.x; sv[cc][half*4+1] = v.y;
            sv[cc][half*4+2] = v.z; sv[cc][half*4+3] = v.w;
        }
    }
    __syncthreads();

    const int wrp  = tid >> 5;
    const int lane = tid & 31;
    float mx = 0.0f;
    #pragma unroll
    for (int i = 0; i < 16; i++) {
        int c = lane + 32 * i;
        float v = sv[c][wrp];
        v = (v - g_mean[c]) * g_rstd[c];
        v = v * gamma[c] + beta[c];
        v = gelu_exact(v);
        sv[c][wrp] = v;
        mx = fmaxf(mx, fabsf(v));
    }
    #pragma unroll
    for (int o = 16; o; o >>= 1) mx = fmaxf(mx, __shfl_xor_sync(0xffffffffu, mx, o));
    float amax = fmaxf(mx, 1e-5f);
    float qscale = 127.0f / amax;
    if (lane == 0) g_ascale[b * Ll + l0 + wrp] = amax * (1.0f / 127.0f);
    #pragma unroll
    for (int i = 0; i < 16; i++) {
        int c = lane + 32 * i;
        float q = rintf(sv[c][wrp] * qscale);
        q = fminf(fmaxf(q, -128.0f), 127.0f);
        qs[wrp][c] = (unsigned char)(signed char)(int)q;
    }
    __syncthreads();

    for (int idx = tid; idx < 1024; idx += 256) {
        int t = idx >> 7;
        int g = idx & 127;
        uchar4 u = *reinterpret_cast<const uchar4*>(&qs[t][g * 4]);
        int packed = (int)u.x | ((int)u.y << 8) | ((int)u.z << 16) | ((int)u.w << 24);
        g_qact[(b * Ll + l0 + t) * 128 + g] = packed;
    }
}

// ---------------------------------------------------------------------------
// BitLinear int8 GEMM (dp4a, exact) + gelu + residual.
// ---------------------------------------------------------------------------
__global__ __launch_bounds__(256) void gemm_kernel(const float* __restrict__ x,
                                                   float* __restrict__ out)
{
    const int b  = blockIdx.z;
    const int o0 = blockIdx.y * 64;
    const int l0 = blockIdx.x * 64;
    const int tid = threadIdx.x;
    const int tx = tid & 15;
    const int ty = tid >> 4;
    __shared__ int qsm[64][17];
    __shared__ int tsm[64][17];
    int acc[4][4] = {};

    for (int kc = 0; kc < 128; kc += 16) {
        for (int idx = tid; idx < 1024; idx += 256) {
            int r = idx >> 4, k = idx & 15;
            qsm[r][k] = g_qact[(b * Ll + l0 + r) * 128 + kc + k];
            tsm[r][k] = g_qw[(o0 + r) * 128 + kc + k];
        }
        __syncthreads();
        #pragma unroll
        for (int k = 0; k < 16; k++) {
            int qv[4], tv[4];
            #pragma unroll
            for (int j = 0; j < 4; j++) qv[j] = qsm[tx * 4 + j][k];
            #pragma unroll
            for (int i = 0; i < 4; i++) tv[i] = tsm[ty * 4 + i][k];
            #pragma unroll
            for (int i = 0; i < 4; i++)
                #pragma unroll
                for (int j = 0; j < 4; j++)
                    acc[i][j] = __dp4a(qv[j], tv[i], acc[i][j]);
        }
        __syncthreads();
    }

    const float wm = g_wmean;
    float as[4];
    #pragma unroll
    for (int j = 0; j < 4; j++) as[j] = g_ascale[b * Ll + l0 + tx * 4 + j] * wm;
    #pragma unroll
    for (int i = 0; i < 4; i++) {
        int o = o0 + ty * 4 + i;
        const float4 xr = *reinterpret_cast<const float4*>(
            x + (size_t)b * CL + (size_t)o * Ll + l0 + tx * 4);
        float4 r;
        r.x = gelu_exact((float)acc[i][0] * as[0]) + xr.x;
        r.y = gelu_exact((float)acc[i][1] * as[1]) + xr.y;
        r.z = gelu_exact((float)acc[i][2] * as[2]) + xr.z;
        r.w = gelu_exact((float)acc[i][3] * as[3]) + xr.w;
        *reinterpret_cast<float4*>(out + (size_t)b * CL + (size_t)o * Ll + l0 + tx * 4) = r;
    }
}

// ---------------------------------------------------------------------------
extern "C" void kernel_launch(void* const* d_in, const int* in_sizes, int n_in,
                              void* d_out, int out_size)
{
    const float* x      = (const float*)d_in[0];
    const float* conv_w = (const float*)d_in[1];
    const float* conv_b = (const float*)d_in[2];
    const float* gamma  = (const float*)d_in[3];
    const float* beta   = (const float*)d_in[4];
    const float* proj_w = (const float*)d_in[5];
    float* out = (float*)d_out;

    cudaFuncSetAttribute(conv_mma_kernel,
                         cudaFuncAttributeMaxDynamicSharedMemorySize, CONV_SMEM);

    // order chosen so ncu -s 5 -c 1 lands on conv_mma_kernel (launch #6)
    wred1_kernel<<<64, 256>>>(proj_w);
    wred2_kernel<<<1, 64>>>();
    wquant_kernel<<<256, 256>>>(proj_w);
    xsplit_kernel<<<dim3(16, 8, 32), 256>>>(x);
    wsplit_kernel<<<512, 256>>>(conv_w);
    conv_mma_kernel<<<dim3(4, 4, 32), 256, CONV_SMEM>>>(conv_b);
    stats_kernel<<<512, 256>>>();
    bnq_kernel<<<dim3(128, 32), 256>>>(gamma, beta);
    gemm_kernel<<<dim3(16, 8, 32), 256>>>(x, out);
}